// round 13
// baseline (speedup 1.0000x reference)
#include <cuda_runtime.h>
#include <cuda_bf16.h>
#include <cuda_fp16.h>
#include <cstdint>

#define BATCH 8
#define NN    2048
#define KDIM  256
#define DOUT  64
#define ALPHA 0.2f

// ---------------- scratch ----------------
__device__ __half g_WhT[BATCH * DOUT * NN];   // [b][d][j] fp16, 2MB
__device__ float g_s1[BATCH * NN];
__device__ float g_s2[BATCH * NN];
__device__ float g_u[BATCH * NN];             // exp(s2)
__device__ float g_v[BATCH * NN];             // exp(alpha*s2)
__device__ unsigned int g_s2max_u[BATCH];     // order-preserving float keys

// ---------------- helpers ----------------
__device__ __forceinline__ uint32_t smem_u32(const void* p) {
    uint32_t a;
    asm("{ .reg .u64 t; cvta.to.shared.u64 t, %1; cvt.u32.u64 %0, t; }" : "=r"(a) : "l"(p));
    return a;
}
__device__ __forceinline__ void ldsm4(uint32_t (&r)[4], uint32_t addr) {
    asm volatile("ldmatrix.sync.aligned.m8n8.x4.shared.b16 {%0,%1,%2,%3}, [%4];"
                 : "=r"(r[0]), "=r"(r[1]), "=r"(r[2]), "=r"(r[3]) : "r"(addr));
}
__device__ __forceinline__ void mma_bf16(float (&d)[4], const uint32_t (&a)[4],
                                         uint32_t b0, uint32_t b1) {
    asm volatile("mma.sync.aligned.m16n8k16.row.col.f32.bf16.bf16.f32 "
                 "{%0,%1,%2,%3}, {%4,%5,%6,%7}, {%8,%9}, {%0,%1,%2,%3};"
                 : "+f"(d[0]), "+f"(d[1]), "+f"(d[2]), "+f"(d[3])
                 : "r"(a[0]), "r"(a[1]), "r"(a[2]), "r"(a[3]), "r"(b0), "r"(b1));
}
__device__ __forceinline__ void mma_f16(float (&d)[4], const uint32_t (&a)[4],
                                        uint32_t b0, uint32_t b1) {
    asm volatile("mma.sync.aligned.m16n8k16.row.col.f32.f16.f16.f32 "
                 "{%0,%1,%2,%3}, {%4,%5,%6,%7}, {%8,%9}, {%0,%1,%2,%3};"
                 : "+f"(d[0]), "+f"(d[1]), "+f"(d[2]), "+f"(d[3])
                 : "r"(a[0]), "r"(a[1]), "r"(a[2]), "r"(a[3]), "r"(b0), "r"(b1));
}
__device__ __forceinline__ uint32_t pkbf2(float x, float y) {
    __nv_bfloat162 t = __floats2bfloat162_rn(x, y);
    return *reinterpret_cast<uint32_t*>(&t);
}
__device__ __forceinline__ uint32_t hibits2(float x, float y) {
    return __byte_perm(__float_as_uint(x), __float_as_uint(y), 0x7632);
}
__device__ __forceinline__ float resid(float x) {
    return x - __uint_as_float(__float_as_uint(x) & 0xFFFF0000u);
}
__device__ __forceinline__ uint32_t pkhf2(float x, float y) {
    __half2 t = __floats2half2_rn(x, y);
    return *reinterpret_cast<uint32_t*>(&t);
}
__device__ __forceinline__ uint32_t fkey(float f) {
    const uint32_t b = __float_as_uint(f);
    return b ^ ((uint32_t)((int)b >> 31) | 0x80000000u);
}
__device__ __forceinline__ float funkey(uint32_t k) {
    const uint32_t b = (k & 0x80000000u) ? (k ^ 0x80000000u) : ~k;
    return __uint_as_float(b);
}
__device__ __forceinline__ uint32_t hmul2u(uint32_t a, uint32_t b) {
    __half2 r = __hmul2(*reinterpret_cast<__half2*>(&a), *reinterpret_cast<__half2*>(&b));
    return *reinterpret_cast<uint32_t*>(&r);
}
__device__ __forceinline__ uint32_t hmax2u(uint32_t a, uint32_t b) {
    __half2 r = __hmax2(*reinterpret_cast<__half2*>(&a), *reinterpret_cast<__half2*>(&b));
    return *reinterpret_cast<uint32_t*>(&r);
}
__device__ __forceinline__ float hsum2u(uint32_t a) {
    __half2 h = *reinterpret_cast<__half2*>(&a);
    return __low2float(h) + __high2float(h);
}

// ============================================================
// Kernel A (HMMA): Wh = h @ W. 256 CTAs x 64 rows, 8 warps, 2 CTAs/SM.
// Emits s1, s2, u, v, s2max key, WhT fp16. (unchanged, proven)
// ============================================================
#define WOFF_HH 0
#define WOFF_HL 8192
#define WOFF_WH 16384
#define WOFF_WL 24576
#define WOFF_TR 0
#define WOFF_PS 32768
#define WH_SMEM 33792

__global__ __launch_bounds__(256, 2) void wh_kernel(const float* __restrict__ h,
                                                    const float* __restrict__ W,
                                                    const float* __restrict__ a) {
    extern __shared__ char sw[];
    const uint32_t smb = smem_u32(sw);
    const int tid = threadIdx.x;
    const int wid = tid >> 5, lid = tid & 31;
    const int gi0 = blockIdx.x * 64;
    const int b = gi0 >> 11;
    const int rowb = gi0 & 2047;

    float acc[4][4];
    #pragma unroll
    for (int n = 0; n < 4; n++)
        #pragma unroll
        for (int k = 0; k < 4; k++) acc[n][k] = 0.f;

    const int mq = wid & 3, nh = wid >> 2;
    const int rr = lid & 7, q = lid >> 3, qh = q >> 1, ql = q & 1;
    const int rowA = mq * 16 + rr + (ql << 3);
    const uint32_t baseA = (uint32_t)(rowA * 128);
    const int xA = rowA & 7;
    const int rbB = nh * 32 + (qh << 3) + rr;

    const int hrow = tid >> 2, hq = tid & 3;
    const float* hsrc = h + (size_t)(gi0 + hrow) * KDIM + hq * 16;
    const int wdd = tid >> 2, wkg = tid & 3;

    for (int kt = 0; kt < 4; kt++) {
        __syncthreads();
        #pragma unroll
        for (int g = 0; g < 2; g++) {
            const float4 f0 = *reinterpret_cast<const float4*>(hsrc + kt * 64 + g * 8);
            const float4 f1 = *reinterpret_cast<const float4*>(hsrc + kt * 64 + g * 8 + 4);
            uint4 hi4, lo4;
            hi4.x = hibits2(f0.x, f0.y); hi4.y = hibits2(f0.z, f0.w);
            hi4.z = hibits2(f1.x, f1.y); hi4.w = hibits2(f1.z, f1.w);
            lo4.x = pkbf2(resid(f0.x), resid(f0.y));
            lo4.y = pkbf2(resid(f0.z), resid(f0.w));
            lo4.z = pkbf2(resid(f1.x), resid(f1.y));
            lo4.w = pkbf2(resid(f1.z), resid(f1.w));
            const int gran = hq * 2 + g;
            const uint32_t addr = (uint32_t)(hrow * 128 + ((gran ^ (hrow & 7)) << 4));
            *reinterpret_cast<uint4*>(sw + WOFF_HH + addr) = hi4;
            *reinterpret_cast<uint4*>(sw + WOFF_HL + addr) = lo4;
        }
        {
            uint32_t hi[8], lo[8];
            #pragma unroll
            for (int t = 0; t < 8; t++) {
                const float x0 = W[(kt * 64 + wkg * 16 + 2 * t) * DOUT + wdd];
                const float x1 = W[(kt * 64 + wkg * 16 + 2 * t + 1) * DOUT + wdd];
                hi[t] = hibits2(x0, x1);
                lo[t] = pkbf2(resid(x0), resid(x1));
            }
            const uint32_t a0 = (uint32_t)(wdd * 128 + (((wkg * 2) ^ (wdd & 7)) << 4));
            const uint32_t a1 = (uint32_t)(wdd * 128 + (((wkg * 2 + 1) ^ (wdd & 7)) << 4));
            *reinterpret_cast<uint4*>(sw + WOFF_WH + a0) = make_uint4(hi[0], hi[1], hi[2], hi[3]);
            *reinterpret_cast<uint4*>(sw + WOFF_WH + a1) = make_uint4(hi[4], hi[5], hi[6], hi[7]);
            *reinterpret_cast<uint4*>(sw + WOFF_WL + a0) = make_uint4(lo[0], lo[1], lo[2], lo[3]);
            *reinterpret_cast<uint4*>(sw + WOFF_WL + a1) = make_uint4(lo[4], lo[5], lo[6], lo[7]);
        }
        __syncthreads();
        #pragma unroll
        for (int t = 0; t < 4; t++) {
            uint32_t Ah[4], Al[4];
            const uint32_t ua = baseA + (uint32_t)(((2 * t + qh) ^ xA) << 4);
            ldsm4(Ah, smb + WOFF_HH + ua);
            ldsm4(Al, smb + WOFF_HL + ua);
            #pragma unroll
            for (int ntp = 0; ntp < 2; ntp++) {
                const int rowB = rbB + ntp * 16;
                const uint32_t ab = (uint32_t)(rowB * 128 + (((2 * t + ql) ^ (rowB & 7)) << 4));
                uint32_t Bh[4], Bl[4];
                ldsm4(Bh, smb + WOFF_WH + ab);
                ldsm4(Bl, smb + WOFF_WL + ab);
                mma_bf16(acc[2 * ntp],     Ah, Bh[0], Bh[1]);
                mma_bf16(acc[2 * ntp],     Ah, Bl[0], Bl[1]);
                mma_bf16(acc[2 * ntp],     Al, Bh[0], Bh[1]);
                mma_bf16(acc[2 * ntp + 1], Ah, Bh[2], Bh[3]);
                mma_bf16(acc[2 * ntp + 1], Ah, Bl[2], Bl[3]);
                mma_bf16(acc[2 * ntp + 1], Al, Bh[2], Bh[3]);
            }
        }
    }
    __syncthreads();

    const int r0 = mq * 16 + (lid >> 2), r1 = r0 + 8;
    float s1r0 = 0.f, s2r0 = 0.f, s1r1 = 0.f, s2r1 = 0.f;
    __half* tr = reinterpret_cast<__half*>(sw + WOFF_TR);
    float* ps1 = reinterpret_cast<float*>(sw + WOFF_PS);
    float* ps2 = ps1 + 128;
    #pragma unroll
    for (int nt = 0; nt < 4; nt++) {
        const int d0 = nh * 32 + nt * 8 + (lid & 3) * 2;
        const float a10 = a[d0], a11 = a[d0 + 1];
        const float a20 = a[64 + d0], a21 = a[64 + d0 + 1];
        s1r0 = fmaf(acc[nt][0], a10, fmaf(acc[nt][1], a11, s1r0));
        s2r0 = fmaf(acc[nt][0], a20, fmaf(acc[nt][1], a21, s2r0));
        s1r1 = fmaf(acc[nt][2], a10, fmaf(acc[nt][3], a11, s1r1));
        s2r1 = fmaf(acc[nt][2], a20, fmaf(acc[nt][3], a21, s2r1));
        tr[(d0 + 0) * 64 + r0] = __float2half_rn(acc[nt][0]);
        tr[(d0 + 1) * 64 + r0] = __float2half_rn(acc[nt][1]);
        tr[(d0 + 0) * 64 + r1] = __float2half_rn(acc[nt][2]);
        tr[(d0 + 1) * 64 + r1] = __float2half_rn(acc[nt][3]);
    }
    #pragma unroll
    for (int off = 1; off <= 2; off <<= 1) {
        s1r0 += __shfl_xor_sync(0xffffffffu, s1r0, off);
        s2r0 += __shfl_xor_sync(0xffffffffu, s2r0, off);
        s1r1 += __shfl_xor_sync(0xffffffffu, s1r1, off);
        s2r1 += __shfl_xor_sync(0xffffffffu, s2r1, off);
    }
    if ((lid & 3) == 0) {
        ps1[nh * 64 + r0] = s1r0; ps2[nh * 64 + r0] = s2r0;
        ps1[nh * 64 + r1] = s1r1; ps2[nh * 64 + r1] = s2r1;
    }
    __syncthreads();

    if (tid < 64) {
        const float s1 = ps1[tid] + ps1[64 + tid];
        const float s2 = ps2[tid] + ps2[64 + tid];
        g_s1[gi0 + tid] = s1;
        g_s2[gi0 + tid] = s2;
        g_u[gi0 + tid] = __expf(s2);
        g_v[gi0 + tid] = __expf(ALPHA * s2);
        float m = s2;
        #pragma unroll
        for (int off = 16; off; off >>= 1) m = fmaxf(m, __shfl_down_sync(0xffffffffu, m, off));
        if ((tid & 31) == 0) atomicMax(&g_s2max_u[b], fkey(m));
    }

    #pragma unroll
    for (int c = 0; c < 2; c++) {
        const int idx = tid + 256 * c;
        const int d = idx >> 3;
        const int c8 = idx & 7;
        const uint4 val = *reinterpret_cast<const uint4*>(tr + d * 64 + c8 * 8);
        *reinterpret_cast<uint4*>(g_WhT + ((size_t)(b * DOUT + d)) * NN + rowb + c8 * 8) = val;
    }
}

// ============================================================
// Kernel B: barrier-free streaming GAT main.
// 512 CTAs x 32 rows, 8 warps. Warp = full 32r x 64d x 256-j slice.
// P fragments built in registers (factorized p, half2 ops);
// W fragments LDG'd directly from L2-resident g_WhT.
// No smem staging / barriers in mainloop. Epilogue: cross-warp k-reduce.
// ============================================================
#define GOFF_U2   0
#define GOFF_V2   4096
#define GOFF_A2   8192
#define GOFF_B2   8320
#define GOFF_RED  8448
#define GOFF_ZRED 73984
#define GAT_SMEM  75008

__global__ __launch_bounds__(256, 2) void gat_main(const int* __restrict__ adj,
                                                   float* __restrict__ out) {
    extern __shared__ char sm[];
    const int tid = threadIdx.x;
    const int wid = tid >> 5, lid = tid & 31;
    const int gi0 = blockIdx.x * 32;
    const int b = gi0 >> 11;

    // ---- prologue: pack u'/v' half2 arrays; A''/B'' broadcast half2 ----
    const float s2m = funkey(g_s2max_u[b]);
    {
        const float su = __expf(-s2m);
        const float sv = __expf(-ALPHA * s2m);
        #pragma unroll
        for (int c = 0; c < 2; c++) {
            const float4 uu = reinterpret_cast<const float4*>(g_u + b * NN)[tid + 256 * c];
            const float4 vv = reinterpret_cast<const float4*>(g_v + b * NN)[tid + 256 * c];
            reinterpret_cast<uint2*>(sm + GOFF_U2)[tid + 256 * c] =
                make_uint2(pkhf2(uu.x * su, uu.y * su), pkhf2(uu.z * su, uu.w * su));
            reinterpret_cast<uint2*>(sm + GOFF_V2)[tid + 256 * c] =
                make_uint2(pkhf2(vv.x * sv, vv.y * sv), pkhf2(vv.z * sv, vv.w * sv));
        }
    }
    if (tid < 32) {
        const float s1 = g_s1[gi0 + tid];
        const float t = s1 + s2m;
        const float m = (t > 0.f) ? t : ALPHA * t;
        const float A = 0.5f * __expf(t - m);
        const float B = 0.5f * __expf(ALPHA * t - m);
        reinterpret_cast<uint32_t*>(sm + GOFF_A2)[tid] = pkhf2(A, A);
        reinterpret_cast<uint32_t*>(sm + GOFF_B2)[tid] = pkhf2(B, B);
    }
    __syncthreads();

    // ---- lane geometry ----
    const int r = lid >> 2;            // fragment row 0..7
    const int kl2 = (lid & 3) * 2;     // k-pair offset
    const int j0 = wid * 256;          // warp's j slice

    uint32_t A2[4], B2[4];
    #pragma unroll
    for (int rm = 0; rm < 4; rm++) {
        A2[rm] = reinterpret_cast<uint32_t*>(sm + GOFF_A2)[rm * 8 + r];
        B2[rm] = reinterpret_cast<uint32_t*>(sm + GOFF_B2)[rm * 8 + r];
    }

    float acc[16][4];                  // [mt*8 + nt][4]
    #pragma unroll
    for (int n = 0; n < 16; n++)
        #pragma unroll
        for (int k = 0; k < 4; k++) acc[n][k] = 0.f;
    float zacc[4] = {0.f, 0.f, 0.f, 0.f};

    const int* a0p = adj + (size_t)(gi0 + r) * NN + j0 + kl2;
    const __half* wbase = g_WhT + ((size_t)(b * DOUT + r)) * NN + j0 + kl2;
    const uint32_t* usm = reinterpret_cast<const uint32_t*>(sm + GOFF_U2) + (j0 >> 1) + (lid & 3);
    const uint32_t* vsm = reinterpret_cast<const uint32_t*>(sm + GOFF_V2) + (j0 >> 1) + (lid & 3);

    // ---- barrier-free mainloop: 16 k16-steps over the warp's 256-j slice ----
    for (int ks = 0; ks < 16; ks++) {
        const int o = ks * 16;

        int2 ad[8];
        #pragma unroll
        for (int rm = 0; rm < 4; rm++) {
            ad[2 * rm]     = *reinterpret_cast<const int2*>(a0p + (size_t)(8 * rm) * NN + o);
            ad[2 * rm + 1] = *reinterpret_cast<const int2*>(a0p + (size_t)(8 * rm) * NN + o + 8);
        }
        const uint32_t up0 = usm[ks * 8],     vp0 = vsm[ks * 8];
        const uint32_t up1 = usm[ks * 8 + 4], vp1 = vsm[ks * 8 + 4];

        uint32_t pA[2][4];
        #pragma unroll
        for (int rm = 0; rm < 4; rm++) {
            const uint32_t m0 = (uint32_t)ad[2 * rm].x * 0x3C00u +
                                (uint32_t)ad[2 * rm].y * 0x3C000000u;
            const uint32_t m1 = (uint32_t)ad[2 * rm + 1].x * 0x3C00u +
                                (uint32_t)ad[2 * rm + 1].y * 0x3C000000u;
            const uint32_t plo = hmul2u(hmax2u(hmul2u(A2[rm], up0), hmul2u(B2[rm], vp0)), m0);
            const uint32_t phi = hmul2u(hmax2u(hmul2u(A2[rm], up1), hmul2u(B2[rm], vp1)), m1);
            zacc[rm] += hsum2u(plo) + hsum2u(phi);
            const int mt = rm >> 1, sl = rm & 1;
            pA[mt][sl] = plo;
            pA[mt][sl + 2] = phi;
        }

        #pragma unroll
        for (int nt = 0; nt < 8; nt++) {
            const __half* wp = wbase + (size_t)(nt * 8) * NN + o;
            const uint32_t b0 = *reinterpret_cast<const uint32_t*>(wp);
            const uint32_t b1 = *reinterpret_cast<const uint32_t*>(wp + 8);
            mma_f16(acc[nt],     pA[0], b0, b1);
            mma_f16(acc[8 + nt], pA[1], b0, b1);
        }
    }

    // ---- epilogue: z shfl-reduce, stage partials, barrier, k-reduce + store ----
    #pragma unroll
    for (int rm = 0; rm < 4; rm++) {
        zacc[rm] += __shfl_xor_sync(0xffffffffu, zacc[rm], 1);
        zacc[rm] += __shfl_xor_sync(0xffffffffu, zacc[rm], 2);
    }
    if ((lid & 3) == 0) {
        float* zr = reinterpret_cast<float*>(sm + GOFF_ZRED);
        #pragma unroll
        for (int rm = 0; rm < 4; rm++) zr[wid * 32 + rm * 8 + r] = zacc[rm];
    }
    {
        float4* red4 = reinterpret_cast<float4*>(sm + GOFF_RED);
        #pragma unroll
        for (int t = 0; t < 16; t++)
            red4[(wid * 16 + t) * 32 + lid] =
                make_float4(acc[t][0], acc[t][1], acc[t][2], acc[t][3]);
    }
    __syncthreads();

    {
        const float4* red4 = reinterpret_cast<const float4*>(sm + GOFF_RED);
        const float* zr = reinterpret_cast<const float*>(sm + GOFF_ZRED);
        #pragma unroll
        for (int s = tid; s < 512; s += 256) {
            const int t16 = s >> 5, sl = s & 31;
            float4 v = red4[t16 * 32 + sl];
            #pragma unroll
            for (int w = 1; w < 8; w++) {
                const float4 o = red4[(w * 16 + t16) * 32 + sl];
                v.x += o.x; v.y += o.y; v.z += o.z; v.w += o.w;
            }
            const int mt = t16 >> 3, nt = t16 & 7;
            const int row0 = mt * 16 + (sl >> 2), row1 = row0 + 8;
            float z0 = 0.f, z1 = 0.f;
            #pragma unroll
            for (int w = 0; w < 8; w++) { z0 += zr[w * 32 + row0]; z1 += zr[w * 32 + row1]; }
            const float i0 = 1.f / z0, i1 = 1.f / z1;
            *reinterpret_cast<float2*>(out + (size_t)(gi0 + row0) * DOUT + nt * 8 + (sl & 3) * 2) =
                make_float2(v.x * i0, v.y * i0);
            *reinterpret_cast<float2*>(out + (size_t)(gi0 + row1) * DOUT + nt * 8 + (sl & 3) * 2) =
                make_float2(v.z * i1, v.w * i1);
        }
    }
}

// ============================================================
extern "C" void kernel_launch(void* const* d_in, const int* in_sizes, int n_in,
                              void* d_out, int out_size) {
    const float* h   = (const float*)d_in[0];
    const int*   adj = (const int*)d_in[1];
    const float* W   = (const float*)d_in[2];
    const float* a   = (const float*)d_in[3];
    float* out = (float*)d_out;

    cudaFuncSetAttribute(gat_main, cudaFuncAttributeMaxDynamicSharedMemorySize, GAT_SMEM);
    cudaFuncSetAttribute(wh_kernel, cudaFuncAttributeMaxDynamicSharedMemorySize, WH_SMEM);

    wh_kernel<<<(BATCH * NN) / 64, 256, WH_SMEM>>>(h, W, a);
    gat_main<<<(BATCH * NN) / 32, 256, GAT_SMEM>>>(adj, out);
}

// round 14
// speedup vs baseline: 1.2191x; 1.2191x over previous
#include <cuda_runtime.h>
#include <cuda_bf16.h>
#include <cuda_fp16.h>
#include <cstdint>

#define BATCH 8
#define NN    2048
#define KDIM  256
#define DOUT  64
#define ALPHA 0.2f

// ---------------- scratch ----------------
__device__ __half g_WhT[BATCH * DOUT * NN];   // [b][d][j] fp16, 2MB
__device__ float g_s1[BATCH * NN];
__device__ float g_s2[BATCH * NN];
__device__ float g_u[BATCH * NN];             // exp(s2)
__device__ float g_v[BATCH * NN];             // exp(alpha*s2)
__device__ unsigned int g_s2max_u[BATCH];     // order-preserving float keys

// ---------------- helpers ----------------
__device__ __forceinline__ uint32_t smem_u32(const void* p) {
    uint32_t a;
    asm("{ .reg .u64 t; cvta.to.shared.u64 t, %1; cvt.u32.u64 %0, t; }" : "=r"(a) : "l"(p));
    return a;
}
__device__ __forceinline__ void ldsm4(uint32_t (&r)[4], uint32_t addr) {
    asm volatile("ldmatrix.sync.aligned.m8n8.x4.shared.b16 {%0,%1,%2,%3}, [%4];"
                 : "=r"(r[0]), "=r"(r[1]), "=r"(r[2]), "=r"(r[3]) : "r"(addr));
}
__device__ __forceinline__ void mma_bf16(float (&d)[4], const uint32_t (&a)[4],
                                         uint32_t b0, uint32_t b1) {
    asm volatile("mma.sync.aligned.m16n8k16.row.col.f32.bf16.bf16.f32 "
                 "{%0,%1,%2,%3}, {%4,%5,%6,%7}, {%8,%9}, {%0,%1,%2,%3};"
                 : "+f"(d[0]), "+f"(d[1]), "+f"(d[2]), "+f"(d[3])
                 : "r"(a[0]), "r"(a[1]), "r"(a[2]), "r"(a[3]), "r"(b0), "r"(b1));
}
__device__ __forceinline__ void mma_f16(float (&d)[4], const uint32_t (&a)[4],
                                        uint32_t b0, uint32_t b1) {
    asm volatile("mma.sync.aligned.m16n8k16.row.col.f32.f16.f16.f32 "
                 "{%0,%1,%2,%3}, {%4,%5,%6,%7}, {%8,%9}, {%0,%1,%2,%3};"
                 : "+f"(d[0]), "+f"(d[1]), "+f"(d[2]), "+f"(d[3])
                 : "r"(a[0]), "r"(a[1]), "r"(a[2]), "r"(a[3]), "r"(b0), "r"(b1));
}
__device__ __forceinline__ uint32_t pkbf2(float x, float y) {
    __nv_bfloat162 t = __floats2bfloat162_rn(x, y);
    return *reinterpret_cast<uint32_t*>(&t);
}
__device__ __forceinline__ uint32_t hibits2(float x, float y) {
    return __byte_perm(__float_as_uint(x), __float_as_uint(y), 0x7632);
}
__device__ __forceinline__ float resid(float x) {
    return x - __uint_as_float(__float_as_uint(x) & 0xFFFF0000u);
}
__device__ __forceinline__ uint32_t pkhf2(float x, float y) {
    __half2 t = __floats2half2_rn(x, y);
    return *reinterpret_cast<uint32_t*>(&t);
}
__device__ __forceinline__ uint32_t fkey(float f) {
    const uint32_t b = __float_as_uint(f);
    return b ^ ((uint32_t)((int)b >> 31) | 0x80000000u);
}
__device__ __forceinline__ float funkey(uint32_t k) {
    const uint32_t b = (k & 0x80000000u) ? (k ^ 0x80000000u) : ~k;
    return __uint_as_float(b);
}
__device__ __forceinline__ uint32_t hmul2u(uint32_t a, uint32_t b) {
    __half2 r = __hmul2(*reinterpret_cast<__half2*>(&a), *reinterpret_cast<__half2*>(&b));
    return *reinterpret_cast<uint32_t*>(&r);
}
__device__ __forceinline__ uint32_t hmax2u(uint32_t a, uint32_t b) {
    __half2 r = __hmax2(*reinterpret_cast<__half2*>(&a), *reinterpret_cast<__half2*>(&b));
    return *reinterpret_cast<uint32_t*>(&r);
}
__device__ __forceinline__ float hsum2u(uint32_t a) {
    __half2 h = *reinterpret_cast<__half2*>(&a);
    return __low2float(h) + __high2float(h);
}
#define CP_ASYNC16(dst, src) \
    asm volatile("cp.async.cg.shared.global [%0], [%1], 16;" :: "r"(dst), "l"(src) : "memory")
#define CP_COMMIT() asm volatile("cp.async.commit_group;" ::: "memory")
#define CP_WAIT0()  asm volatile("cp.async.wait_group 0;" ::: "memory")

// ============================================================
// Kernel A (HMMA): Wh = h @ W. (unchanged, proven)
// ============================================================
#define WOFF_HH 0
#define WOFF_HL 8192
#define WOFF_WH 16384
#define WOFF_WL 24576
#define WOFF_TR 0
#define WOFF_PS 32768
#define WH_SMEM 33792

__global__ __launch_bounds__(256, 2) void wh_kernel(const float* __restrict__ h,
                                                    const float* __restrict__ W,
                                                    const float* __restrict__ a) {
    extern __shared__ char sw[];
    const uint32_t smb = smem_u32(sw);
    const int tid = threadIdx.x;
    const int wid = tid >> 5, lid = tid & 31;
    const int gi0 = blockIdx.x * 64;
    const int b = gi0 >> 11;
    const int rowb = gi0 & 2047;

    float acc[4][4];
    #pragma unroll
    for (int n = 0; n < 4; n++)
        #pragma unroll
        for (int k = 0; k < 4; k++) acc[n][k] = 0.f;

    const int mq = wid & 3, nh = wid >> 2;
    const int rr = lid & 7, q = lid >> 3, qh = q >> 1, ql = q & 1;
    const int rowA = mq * 16 + rr + (ql << 3);
    const uint32_t baseA = (uint32_t)(rowA * 128);
    const int xA = rowA & 7;
    const int rbB = nh * 32 + (qh << 3) + rr;

    const int hrow = tid >> 2, hq = tid & 3;
    const float* hsrc = h + (size_t)(gi0 + hrow) * KDIM + hq * 16;
    const int wdd = tid >> 2, wkg = tid & 3;

    for (int kt = 0; kt < 4; kt++) {
        __syncthreads();
        #pragma unroll
        for (int g = 0; g < 2; g++) {
            const float4 f0 = *reinterpret_cast<const float4*>(hsrc + kt * 64 + g * 8);
            const float4 f1 = *reinterpret_cast<const float4*>(hsrc + kt * 64 + g * 8 + 4);
            uint4 hi4, lo4;
            hi4.x = hibits2(f0.x, f0.y); hi4.y = hibits2(f0.z, f0.w);
            hi4.z = hibits2(f1.x, f1.y); hi4.w = hibits2(f1.z, f1.w);
            lo4.x = pkbf2(resid(f0.x), resid(f0.y));
            lo4.y = pkbf2(resid(f0.z), resid(f0.w));
            lo4.z = pkbf2(resid(f1.x), resid(f1.y));
            lo4.w = pkbf2(resid(f1.z), resid(f1.w));
            const int gran = hq * 2 + g;
            const uint32_t addr = (uint32_t)(hrow * 128 + ((gran ^ (hrow & 7)) << 4));
            *reinterpret_cast<uint4*>(sw + WOFF_HH + addr) = hi4;
            *reinterpret_cast<uint4*>(sw + WOFF_HL + addr) = lo4;
        }
        {
            uint32_t hi[8], lo[8];
            #pragma unroll
            for (int t = 0; t < 8; t++) {
                const float x0 = W[(kt * 64 + wkg * 16 + 2 * t) * DOUT + wdd];
                const float x1 = W[(kt * 64 + wkg * 16 + 2 * t + 1) * DOUT + wdd];
                hi[t] = hibits2(x0, x1);
                lo[t] = pkbf2(resid(x0), resid(x1));
            }
            const uint32_t a0 = (uint32_t)(wdd * 128 + (((wkg * 2) ^ (wdd & 7)) << 4));
            const uint32_t a1 = (uint32_t)(wdd * 128 + (((wkg * 2 + 1) ^ (wdd & 7)) << 4));
            *reinterpret_cast<uint4*>(sw + WOFF_WH + a0) = make_uint4(hi[0], hi[1], hi[2], hi[3]);
            *reinterpret_cast<uint4*>(sw + WOFF_WH + a1) = make_uint4(hi[4], hi[5], hi[6], hi[7]);
            *reinterpret_cast<uint4*>(sw + WOFF_WL + a0) = make_uint4(lo[0], lo[1], lo[2], lo[3]);
            *reinterpret_cast<uint4*>(sw + WOFF_WL + a1) = make_uint4(lo[4], lo[5], lo[6], lo[7]);
        }
        __syncthreads();
        #pragma unroll
        for (int t = 0; t < 4; t++) {
            uint32_t Ah[4], Al[4];
            const uint32_t ua = baseA + (uint32_t)(((2 * t + qh) ^ xA) << 4);
            ldsm4(Ah, smb + WOFF_HH + ua);
            ldsm4(Al, smb + WOFF_HL + ua);
            #pragma unroll
            for (int ntp = 0; ntp < 2; ntp++) {
                const int rowB = rbB + ntp * 16;
                const uint32_t ab = (uint32_t)(rowB * 128 + (((2 * t + ql) ^ (rowB & 7)) << 4));
                uint32_t Bh[4], Bl[4];
                ldsm4(Bh, smb + WOFF_WH + ab);
                ldsm4(Bl, smb + WOFF_WL + ab);
                mma_bf16(acc[2 * ntp],     Ah, Bh[0], Bh[1]);
                mma_bf16(acc[2 * ntp],     Ah, Bl[0], Bl[1]);
                mma_bf16(acc[2 * ntp],     Al, Bh[0], Bh[1]);
                mma_bf16(acc[2 * ntp + 1], Ah, Bh[2], Bh[3]);
                mma_bf16(acc[2 * ntp + 1], Ah, Bl[2], Bl[3]);
                mma_bf16(acc[2 * ntp + 1], Al, Bh[2], Bh[3]);
            }
        }
    }
    __syncthreads();

    const int r0 = mq * 16 + (lid >> 2), r1 = r0 + 8;
    float s1r0 = 0.f, s2r0 = 0.f, s1r1 = 0.f, s2r1 = 0.f;
    __half* tr = reinterpret_cast<__half*>(sw + WOFF_TR);
    float* ps1 = reinterpret_cast<float*>(sw + WOFF_PS);
    float* ps2 = ps1 + 128;
    #pragma unroll
    for (int nt = 0; nt < 4; nt++) {
        const int d0 = nh * 32 + nt * 8 + (lid & 3) * 2;
        const float a10 = a[d0], a11 = a[d0 + 1];
        const float a20 = a[64 + d0], a21 = a[64 + d0 + 1];
        s1r0 = fmaf(acc[nt][0], a10, fmaf(acc[nt][1], a11, s1r0));
        s2r0 = fmaf(acc[nt][0], a20, fmaf(acc[nt][1], a21, s2r0));
        s1r1 = fmaf(acc[nt][2], a10, fmaf(acc[nt][3], a11, s1r1));
        s2r1 = fmaf(acc[nt][2], a20, fmaf(acc[nt][3], a21, s2r1));
        tr[(d0 + 0) * 64 + r0] = __float2half_rn(acc[nt][0]);
        tr[(d0 + 1) * 64 + r0] = __float2half_rn(acc[nt][1]);
        tr[(d0 + 0) * 64 + r1] = __float2half_rn(acc[nt][2]);
        tr[(d0 + 1) * 64 + r1] = __float2half_rn(acc[nt][3]);
    }
    #pragma unroll
    for (int off = 1; off <= 2; off <<= 1) {
        s1r0 += __shfl_xor_sync(0xffffffffu, s1r0, off);
        s2r0 += __shfl_xor_sync(0xffffffffu, s2r0, off);
        s1r1 += __shfl_xor_sync(0xffffffffu, s1r1, off);
        s2r1 += __shfl_xor_sync(0xffffffffu, s2r1, off);
    }
    if ((lid & 3) == 0) {
        ps1[nh * 64 + r0] = s1r0; ps2[nh * 64 + r0] = s2r0;
        ps1[nh * 64 + r1] = s1r1; ps2[nh * 64 + r1] = s2r1;
    }
    __syncthreads();

    if (tid < 64) {
        const float s1 = ps1[tid] + ps1[64 + tid];
        const float s2 = ps2[tid] + ps2[64 + tid];
        g_s1[gi0 + tid] = s1;
        g_s2[gi0 + tid] = s2;
        g_u[gi0 + tid] = __expf(s2);
        g_v[gi0 + tid] = __expf(ALPHA * s2);
        float m = s2;
        #pragma unroll
        for (int off = 16; off; off >>= 1) m = fmaxf(m, __shfl_down_sync(0xffffffffu, m, off));
        if ((tid & 31) == 0) atomicMax(&g_s2max_u[b], fkey(m));
    }

    #pragma unroll
    for (int c = 0; c < 2; c++) {
        const int idx = tid + 256 * c;
        const int d = idx >> 3;
        const int c8 = idx & 7;
        const uint4 val = *reinterpret_cast<const uint4*>(tr + d * 64 + c8 * 8);
        *reinterpret_cast<uint4*>(g_WhT + ((size_t)(b * DOUT + d)) * NN + rowb + c8 * 8) = val;
    }
}

// ============================================================
// Kernel B: fp16 HMMA GAT main, j-tile 128 + cp.async adj staging.
// 256 CTAs x 64 rows, 8 warps (256 thr), 2 CTAs/SM, K-split (2,2,2),
// 16 iterations (half the barriers of R12).
// iter jt: issue cp.async adj(jt+1) [self-staged smem] + W(jt+1) regs
//          -> MMA(jt) -> cp.wait -> build(jt+1) -> bar.
// ============================================================
#define GOFF_PHI(s) ((s) * 16384)
#define GOFF_WHI(s) (32768 + (s) * 16384)
#define GOFF_ADJ 65536
#define GOFF_U2  98304
#define GOFF_V2  102400
#define GOFF_A2  106496
#define GOFF_B2  106752
#define GOFF_ZF  107008
#define GAT_SMEM 107264
#define JTILE    128
#define NITER    (NN / JTILE)

__global__ __launch_bounds__(256, 2) void gat_main(const int* __restrict__ adj,
                                                   float* __restrict__ out) {
    extern __shared__ char sm[];
    const uint32_t smb = smem_u32(sm);
    const int tid = threadIdx.x;
    const int wid = tid >> 5, lid = tid & 31;
    const int gi0 = blockIdx.x * 64;
    const int b = gi0 >> 11;

    float* zf = reinterpret_cast<float*>(sm + GOFF_ZF);

    // ---- prologue: pack u'/v' half2; A''/B'' duplicated half2 ----
    const float s2m = funkey(g_s2max_u[b]);
    {
        const float su = __expf(-s2m);
        const float sv = __expf(-ALPHA * s2m);
        #pragma unroll
        for (int c = 0; c < 2; c++) {
            const float4 uu = reinterpret_cast<const float4*>(g_u + b * NN)[tid + 256 * c];
            const float4 vv = reinterpret_cast<const float4*>(g_v + b * NN)[tid + 256 * c];
            reinterpret_cast<uint2*>(sm + GOFF_U2)[tid + 256 * c] =
                make_uint2(pkhf2(uu.x * su, uu.y * su), pkhf2(uu.z * su, uu.w * su));
            reinterpret_cast<uint2*>(sm + GOFF_V2)[tid + 256 * c] =
                make_uint2(pkhf2(vv.x * sv, vv.y * sv), pkhf2(vv.z * sv, vv.w * sv));
        }
    }
    if (tid < 64) {
        const float s1 = g_s1[gi0 + tid];
        const float t = s1 + s2m;
        const float m = (t > 0.f) ? t : ALPHA * t;
        const float A = 0.5f * __expf(t - m);
        const float B = 0.5f * __expf(ALPHA * t - m);
        reinterpret_cast<uint32_t*>(sm + GOFF_A2)[tid] = pkhf2(A, A);
        reinterpret_cast<uint32_t*>(sm + GOFF_B2)[tid] = pkhf2(B, B);
    }
    __syncthreads();

    // ---- build geometry: thread -> rows prow + 16*i (i<4), 8 j each ----
    const int prow = tid >> 4;
    const int chunk = tid & 15;       // j slice: chunk*8 .. chunk*8+7

    uint32_t A2[4], B2[4];
    #pragma unroll
    for (int i = 0; i < 4; i++) {
        A2[i] = reinterpret_cast<uint32_t*>(sm + GOFF_A2)[prow + 16 * i];
        B2[i] = reinterpret_cast<uint32_t*>(sm + GOFF_B2)[prow + 16 * i];
    }

    float acc[8][4];
    #pragma unroll
    for (int n = 0; n < 8; n++)
        #pragma unroll
        for (int k = 0; k < 4; k++) acc[n][k] = 0.f;
    float zacc[4] = {0.f, 0.f, 0.f, 0.f};

    // ---- MMA geometry: (mq, nq, kq) ----
    const int mq = wid & 1, nq = (wid >> 1) & 1, kq = wid >> 2;
    const int rr = lid & 7, q = lid >> 3, qh = q >> 1, ql = q & 1;
    uint32_t baseA[2]; int xA[2];
    #pragma unroll
    for (int fm = 0; fm < 2; fm++) {
        const int rA = mq * 32 + fm * 16 + rr + (ql << 3);
        baseA[fm] = (uint32_t)(rA * 256);
        xA[fm] = rA & 7;
    }
    uint32_t baseB[2]; int xB[2];
    #pragma unroll
    for (int fn = 0; fn < 2; fn++) {
        const int rB = nq * 32 + fn * 16 + (qh << 3) + rr;
        baseB[fn] = (uint32_t)(rB * 256);
        xB[fn] = rB & 7;
    }

    // ---- W staging: thread = (d = tid>>2, j block (tid&3)*32), 4 x uint4 ----
    const int wdd = tid >> 2, wjb = (tid & 3) * 4;   // chunk base (16B units)
    uint32_t wdst[4];
    #pragma unroll
    for (int c = 0; c < 4; c++)
        wdst[c] = (uint32_t)(wdd * 256 + (((wjb + c) ^ (wdd & 7)) << 4));
    const __half* wsrc = g_WhT + ((size_t)(b * DOUT + wdd)) * NN + (tid & 3) * 32;

    // ---- adj cp.async addressing (self-staged, self-consumed) ----
    const int* asrc = adj + (size_t)(gi0 + prow) * NN + chunk * 8;
    uint32_t adst[4];
    #pragma unroll
    for (int i = 0; i < 4; i++)
        adst[i] = smb + GOFF_ADJ + (uint32_t)((prow + 16 * i) * 512 + chunk * 32);

    const uint32_t uvoff = (uint32_t)(chunk * 16);
    uint32_t swo[4];
    #pragma unroll
    for (int i = 0; i < 4; i++) {
        const int row = prow + 16 * i;
        swo[i] = (uint32_t)(row * 256 + ((chunk ^ (row & 7)) << 4));
    }

    // ---- prologue staging: adj(0) via cp.async; W(0) via regs ----
    #pragma unroll
    for (int i = 0; i < 4; i++) {
        CP_ASYNC16(adst[i], asrc + (size_t)(16 * i) * NN);
        CP_ASYNC16(adst[i] + 16, asrc + (size_t)(16 * i) * NN + 4);
    }
    CP_COMMIT();
    uint4 pwh[4];
    #pragma unroll
    for (int c = 0; c < 4; c++)
        pwh[c] = *reinterpret_cast<const uint4*>(wsrc + c * 8);
    CP_WAIT0();

    // build stage 0
    {
        #pragma unroll
        for (int c = 0; c < 4; c++)
            *reinterpret_cast<uint4*>(sm + GOFF_WHI(0) + wdst[c]) = pwh[c];
        const uint4 up = *reinterpret_cast<const uint4*>(sm + GOFF_U2 + uvoff);
        const uint4 vp = *reinterpret_cast<const uint4*>(sm + GOFF_V2 + uvoff);
        #pragma unroll
        for (int i = 0; i < 4; i++) {
            const int4 a0 = *reinterpret_cast<const int4*>(sm + (adst[i] - smb));
            const int4 a1 = *reinterpret_cast<const int4*>(sm + (adst[i] - smb) + 16);
            const uint32_t m0 = (uint32_t)a0.x * 0x3C00u + (uint32_t)a0.y * 0x3C000000u;
            const uint32_t m1 = (uint32_t)a0.z * 0x3C00u + (uint32_t)a0.w * 0x3C000000u;
            const uint32_t m2 = (uint32_t)a1.x * 0x3C00u + (uint32_t)a1.y * 0x3C000000u;
            const uint32_t m3 = (uint32_t)a1.z * 0x3C00u + (uint32_t)a1.w * 0x3C000000u;
            const uint32_t p0 = hmul2u(hmax2u(hmul2u(A2[i], up.x), hmul2u(B2[i], vp.x)), m0);
            const uint32_t p1 = hmul2u(hmax2u(hmul2u(A2[i], up.y), hmul2u(B2[i], vp.y)), m1);
            const uint32_t p2 = hmul2u(hmax2u(hmul2u(A2[i], up.z), hmul2u(B2[i], vp.z)), m2);
            const uint32_t p3 = hmul2u(hmax2u(hmul2u(A2[i], up.w), hmul2u(B2[i], vp.w)), m3);
            zacc[i] += (hsum2u(p0) + hsum2u(p1)) + (hsum2u(p2) + hsum2u(p3));
            *reinterpret_cast<uint4*>(sm + GOFF_PHI(0) + swo[i]) = make_uint4(p0, p1, p2, p3);
        }
    }
    __syncthreads();

    for (int jt = 0; jt < NITER; jt++) {
        const int cur = jt & 1;
        const bool more = (jt < NITER - 1);
        const int jn = (jt + 1) * JTILE;

        // ---- issue adj(jt+1) cp.async (buffer already consumed by this thread) ----
        if (more) {
            #pragma unroll
            for (int i = 0; i < 4; i++) {
                CP_ASYNC16(adst[i], asrc + (size_t)(16 * i) * NN + jn);
                CP_ASYNC16(adst[i] + 16, asrc + (size_t)(16 * i) * NN + jn + 4);
            }
            CP_COMMIT();
            #pragma unroll
            for (int c = 0; c < 4; c++)
                pwh[c] = *reinterpret_cast<const uint4*>(wsrc + jn + c * 8);
        }

        // ---- MMA on current stage: 4 ksteps x (2 ldsmA + 2 ldsmB + 8 MMA) ----
        {
            const uint32_t oPhi = GOFF_PHI(cur), oWhi = GOFF_WHI(cur);
            #pragma unroll
            for (int t = 0; t < 4; t++) {
                const int ks = kq * 4 + t;
                uint32_t A0[4], A1[4], B0[4], B1[4];
                ldsm4(A0, smb + oPhi + baseA[0] + (uint32_t)(((2 * ks + qh) ^ xA[0]) << 4));
                ldsm4(A1, smb + oPhi + baseA[1] + (uint32_t)(((2 * ks + qh) ^ xA[1]) << 4));
                ldsm4(B0, smb + oWhi + baseB[0] + (uint32_t)(((2 * ks + ql) ^ xB[0]) << 4));
                ldsm4(B1, smb + oWhi + baseB[1] + (uint32_t)(((2 * ks + ql) ^ xB[1]) << 4));
                mma_f16(acc[0], A0, B0[0], B0[1]);
                mma_f16(acc[1], A0, B0[2], B0[3]);
                mma_f16(acc[2], A0, B1[0], B1[1]);
                mma_f16(acc[3], A0, B1[2], B1[3]);
                mma_f16(acc[4], A1, B0[0], B0[1]);
                mma_f16(acc[5], A1, B0[2], B0[3]);
                mma_f16(acc[6], A1, B1[0], B1[1]);
                mma_f16(acc[7], A1, B1[2], B1[3]);
            }
        }

        // ---- build next stage ----
        if (more) {
            const int nxt = cur ^ 1;
            CP_WAIT0();
            #pragma unroll
            for (int c = 0; c < 4; c++)
                *reinterpret_cast<uint4*>(sm + GOFF_WHI(nxt) + wdst[c]) = pwh[c];
            const uint4 up = *reinterpret_cast<const uint4*>(sm + GOFF_U2 + jn * 2 + uvoff);
            const uint4 vp = *reinterpret_cast<const uint4*>(sm + GOFF_V2 + jn * 2 + uvoff);
            #pragma unroll
            for (int i = 0; i < 4; i++) {
                const int4 a0 = *reinterpret_cast<const int4*>(sm + (adst[i] - smb));
                const int4 a1 = *reinterpret_cast<const int4*>(sm + (adst[i] - smb) + 16);
                const uint32_t m0 = (uint32_t)a0.x * 0x3C00u + (uint32_t)a0.y * 0x3C000000u;
                const uint32_t m1 = (uint32_t)a0.z * 0x3C00u + (uint32_t)a0.w * 0x3C000000u;
                const uint32_t m2 = (uint32_t)a1.x * 0x3C00u + (uint32_t)a1.y * 0x3C000000u;
                const uint32_t m3 = (uint32_t)a1.z * 0x3C00u + (uint32_t)a1.w * 0x3C000000u;
                const uint32_t p0 = hmul2u(hmax2u(hmul2u(A2[i], up.x), hmul2u(B2[i], vp.x)), m0);
                const uint32_t p1 = hmul2u(hmax2u(hmul2u(A2[i], up.y), hmul2u(B2[i], vp.y)), m1);
                const uint32_t p2 = hmul2u(hmax2u(hmul2u(A2[i], up.z), hmul2u(B2[i], vp.z)), m2);
                const uint32_t p3 = hmul2u(hmax2u(hmul2u(A2[i], up.w), hmul2u(B2[i], vp.w)), m3);
                zacc[i] += (hsum2u(p0) + hsum2u(p1)) + (hsum2u(p2) + hsum2u(p3));
                *reinterpret_cast<uint4*>(sm + GOFF_PHI(nxt) + swo[i]) = make_uint4(p0, p1, p2, p3);
            }
        }
        __syncthreads();
    }

    // ---- epilogue: z partials + kq-partial acc reduction (as R12) ----
    {
        float* zp = reinterpret_cast<float*>(sm + GOFF_WHI(0));
        #pragma unroll
        for (int i = 0; i < 4; i++) zp[(prow + 16 * i) * 16 + chunk] = zacc[i];
    }
    if (kq == 1) {
        float4* st = reinterpret_cast<float4*>(sm + GOFF_PHI(0));
        const int pair = wid - 4;
        #pragma unroll
        for (int rg = 0; rg < 8; rg++)
            st[pair * 256 + rg * 32 + lid] =
                make_float4(acc[rg][0], acc[rg][1], acc[rg][2], acc[rg][3]);
    }
    __syncthreads();

    if (tid < 64) {
        const float* zp = reinterpret_cast<const float*>(sm + GOFF_WHI(0));
        float z = 0.f;
        #pragma unroll
        for (int t = 0; t < 16; t++) z += zp[tid * 16 + t];
        zf[tid] = z;
    }
    if (kq == 0) {
        const float4* st = reinterpret_cast<const float4*>(sm + GOFF_PHI(0));
        #pragma unroll
        for (int rg = 0; rg < 8; rg++) {
            const float4 v = st[wid * 256 + rg * 32 + lid];
            acc[rg][0] += v.x; acc[rg][1] += v.y; acc[rg][2] += v.z; acc[rg][3] += v.w;
        }
    }
    __syncthreads();

    if (kq == 0) {
        const int rlo = mq * 32 + (lid >> 2);
        #pragma unroll
        for (int fm = 0; fm < 2; fm++) {
            const int r0 = rlo + fm * 16, r1 = r0 + 8;
            const float inv0 = 1.f / zf[r0];
            const float inv1 = 1.f / zf[r1];
            float* o0 = out + (size_t)(gi0 + r0) * DOUT + nq * 32 + (lid & 3) * 2;
            float* o1 = out + (size_t)(gi0 + r1) * DOUT + nq * 32 + (lid & 3) * 2;
            #pragma unroll
            for (int fn = 0; fn < 4; fn++) {
                const int idx = fm * 4 + fn;
                *reinterpret_cast<float2*>(o0 + fn * 8) =
                    make_float2(acc[idx][0] * inv0, acc[idx][1] * inv0);
                *reinterpret_cast<float2*>(o1 + fn * 8) =
                    make_float2(acc[idx][2] * inv1, acc[idx][3] * inv1);
            }
        }
    }
}

// ============================================================
extern "C" void kernel_launch(void* const* d_in, const int* in_sizes, int n_in,
                              void* d_out, int out_size) {
    const float* h   = (const float*)d_in[0];
    const int*   adj = (const int*)d_in[1];
    const float* W   = (const float*)d_in[2];
    const float* a   = (const float*)d_in[3];
    float* out = (float*)d_out;

    cudaFuncSetAttribute(gat_main, cudaFuncAttributeMaxDynamicSharedMemorySize, GAT_SMEM);
    cudaFuncSetAttribute(wh_kernel, cudaFuncAttributeMaxDynamicSharedMemorySize, WH_SMEM);

    wh_kernel<<<(BATCH * NN) / 64, 256, WH_SMEM>>>(h, W, a);
    gat_main<<<(BATCH * NN) / 64, 256, GAT_SMEM>>>(adj, out);
}

// round 15
// speedup vs baseline: 1.4037x; 1.1514x over previous
#include <cuda_runtime.h>
#include <cuda_bf16.h>
#include <cuda_fp16.h>
#include <cstdint>

#define BATCH 8
#define NN    2048
#define KDIM  256
#define DOUT  64
#define ALPHA 0.2f

// ---------------- scratch ----------------
__device__ __half g_WhT[BATCH * DOUT * NN];   // [b][d][j] fp16, 2MB
__device__ float g_s1[BATCH * NN];
__device__ float g_s2[BATCH * NN];
__device__ float g_u[BATCH * NN];             // exp(s2)
__device__ float g_v[BATCH * NN];             // exp(alpha*s2)
__device__ unsigned int g_s2max_u[BATCH];     // order-preserving float keys

// ---------------- helpers ----------------
__device__ __forceinline__ uint32_t smem_u32(const void* p) {
    uint32_t a;
    asm("{ .reg .u64 t; cvta.to.shared.u64 t, %1; cvt.u32.u64 %0, t; }" : "=r"(a) : "l"(p));
    return a;
}
__device__ __forceinline__ void ldsm4(uint32_t (&r)[4], uint32_t addr) {
    asm volatile("ldmatrix.sync.aligned.m8n8.x4.shared.b16 {%0,%1,%2,%3}, [%4];"
                 : "=r"(r[0]), "=r"(r[1]), "=r"(r[2]), "=r"(r[3]) : "r"(addr));
}
__device__ __forceinline__ void mma_bf16(float (&d)[4], const uint32_t (&a)[4],
                                         uint32_t b0, uint32_t b1) {
    asm volatile("mma.sync.aligned.m16n8k16.row.col.f32.bf16.bf16.f32 "
                 "{%0,%1,%2,%3}, {%4,%5,%6,%7}, {%8,%9}, {%0,%1,%2,%3};"
                 : "+f"(d[0]), "+f"(d[1]), "+f"(d[2]), "+f"(d[3])
                 : "r"(a[0]), "r"(a[1]), "r"(a[2]), "r"(a[3]), "r"(b0), "r"(b1));
}
__device__ __forceinline__ void mma_f16(float (&d)[4], const uint32_t (&a)[4],
                                        uint32_t b0, uint32_t b1) {
    asm volatile("mma.sync.aligned.m16n8k16.row.col.f32.f16.f16.f32 "
                 "{%0,%1,%2,%3}, {%4,%5,%6,%7}, {%8,%9}, {%0,%1,%2,%3};"
                 : "+f"(d[0]), "+f"(d[1]), "+f"(d[2]), "+f"(d[3])
                 : "r"(a[0]), "r"(a[1]), "r"(a[2]), "r"(a[3]), "r"(b0), "r"(b1));
}
__device__ __forceinline__ uint32_t pkbf2(float x, float y) {
    __nv_bfloat162 t = __floats2bfloat162_rn(x, y);
    return *reinterpret_cast<uint32_t*>(&t);
}
__device__ __forceinline__ uint32_t hibits2(float x, float y) {
    return __byte_perm(__float_as_uint(x), __float_as_uint(y), 0x7632);
}
__device__ __forceinline__ float resid(float x) {
    return x - __uint_as_float(__float_as_uint(x) & 0xFFFF0000u);
}
__device__ __forceinline__ uint32_t pkhf2(float x, float y) {
    __half2 t = __floats2half2_rn(x, y);
    return *reinterpret_cast<uint32_t*>(&t);
}
__device__ __forceinline__ uint32_t fkey(float f) {
    const uint32_t b = __float_as_uint(f);
    return b ^ ((uint32_t)((int)b >> 31) | 0x80000000u);
}
__device__ __forceinline__ float funkey(uint32_t k) {
    const uint32_t b = (k & 0x80000000u) ? (k ^ 0x80000000u) : ~k;
    return __uint_as_float(b);
}

// ============================================================
// Kernel A (HMMA): Wh = h @ W. 256 CTAs x 64 rows, 8 warps, 2 CTAs/SM.
// NOW with distance-1 register prefetch of h/W chunks.
// Emits s1, s2, u, v, s2max key, WhT fp16.
// ============================================================
#define WOFF_HH 0
#define WOFF_HL 8192
#define WOFF_WH 16384
#define WOFF_WL 24576
#define WOFF_TR 0
#define WOFF_PS 32768
#define WH_SMEM 33792

__global__ __launch_bounds__(256, 2) void wh_kernel(const float* __restrict__ h,
                                                    const float* __restrict__ W,
                                                    const float* __restrict__ a) {
    extern __shared__ char sw[];
    const uint32_t smb = smem_u32(sw);
    const int tid = threadIdx.x;
    const int wid = tid >> 5, lid = tid & 31;
    const int gi0 = blockIdx.x * 64;
    const int b = gi0 >> 11;
    const int rowb = gi0 & 2047;

    float acc[4][4];
    #pragma unroll
    for (int n = 0; n < 4; n++)
        #pragma unroll
        for (int k = 0; k < 4; k++) acc[n][k] = 0.f;

    const int mq = wid & 3, nh = wid >> 2;
    const int rr = lid & 7, q = lid >> 3, qh = q >> 1, ql = q & 1;
    const int rowA = mq * 16 + rr + (ql << 3);
    const uint32_t baseA = (uint32_t)(rowA * 128);
    const int xA = rowA & 7;
    const int rbB = nh * 32 + (qh << 3) + rr;

    const int hrow = tid >> 2, hq = tid & 3;
    const float* hsrc = h + (size_t)(gi0 + hrow) * KDIM + hq * 16;
    const int wdd = tid >> 2, wkg = tid & 3;

    // ---- distance-1 prefetch buffers ----
    float4 hc[4];
    float wc[16];
    #pragma unroll
    for (int g = 0; g < 2; g++) {
        hc[2 * g]     = *reinterpret_cast<const float4*>(hsrc + g * 8);
        hc[2 * g + 1] = *reinterpret_cast<const float4*>(hsrc + g * 8 + 4);
    }
    #pragma unroll
    for (int t = 0; t < 16; t++)
        wc[t] = W[(wkg * 16 + t) * DOUT + wdd];

    for (int kt = 0; kt < 4; kt++) {
        __syncthreads();     // previous MMA done reading smem
        // ---- stage h chunk [64 rows][64 k] hi/lo from regs ----
        #pragma unroll
        for (int g = 0; g < 2; g++) {
            const float4 f0 = hc[2 * g];
            const float4 f1 = hc[2 * g + 1];
            uint4 hi4, lo4;
            hi4.x = hibits2(f0.x, f0.y); hi4.y = hibits2(f0.z, f0.w);
            hi4.z = hibits2(f1.x, f1.y); hi4.w = hibits2(f1.z, f1.w);
            lo4.x = pkbf2(resid(f0.x), resid(f0.y));
            lo4.y = pkbf2(resid(f0.z), resid(f0.w));
            lo4.z = pkbf2(resid(f1.x), resid(f1.y));
            lo4.w = pkbf2(resid(f1.z), resid(f1.w));
            const int gran = hq * 2 + g;
            const uint32_t addr = (uint32_t)(hrow * 128 + ((gran ^ (hrow & 7)) << 4));
            *reinterpret_cast<uint4*>(sw + WOFF_HH + addr) = hi4;
            *reinterpret_cast<uint4*>(sw + WOFF_HL + addr) = lo4;
        }
        // ---- stage W^T chunk [64 d][64 k] hi/lo from regs ----
        {
            uint32_t hi[8], lo[8];
            #pragma unroll
            for (int t = 0; t < 8; t++) {
                hi[t] = hibits2(wc[2 * t], wc[2 * t + 1]);
                lo[t] = pkbf2(resid(wc[2 * t]), resid(wc[2 * t + 1]));
            }
            const uint32_t a0 = (uint32_t)(wdd * 128 + (((wkg * 2) ^ (wdd & 7)) << 4));
            const uint32_t a1 = (uint32_t)(wdd * 128 + (((wkg * 2 + 1) ^ (wdd & 7)) << 4));
            *reinterpret_cast<uint4*>(sw + WOFF_WH + a0) = make_uint4(hi[0], hi[1], hi[2], hi[3]);
            *reinterpret_cast<uint4*>(sw + WOFF_WH + a1) = make_uint4(hi[4], hi[5], hi[6], hi[7]);
            *reinterpret_cast<uint4*>(sw + WOFF_WL + a0) = make_uint4(lo[0], lo[1], lo[2], lo[3]);
            *reinterpret_cast<uint4*>(sw + WOFF_WL + a1) = make_uint4(lo[4], lo[5], lo[6], lo[7]);
        }
        // ---- prefetch kt+1 (covers bar + MMA phase) ----
        if (kt < 3) {
            #pragma unroll
            for (int g = 0; g < 2; g++) {
                hc[2 * g]     = *reinterpret_cast<const float4*>(hsrc + (kt + 1) * 64 + g * 8);
                hc[2 * g + 1] = *reinterpret_cast<const float4*>(hsrc + (kt + 1) * 64 + g * 8 + 4);
            }
            #pragma unroll
            for (int t = 0; t < 16; t++)
                wc[t] = W[((kt + 1) * 64 + wkg * 16 + t) * DOUT + wdd];
        }
        __syncthreads();
        // ---- 3-split bf16 MMA ----
        #pragma unroll
        for (int t = 0; t < 4; t++) {
            uint32_t Ah[4], Al[4];
            const uint32_t ua = baseA + (uint32_t)(((2 * t + qh) ^ xA) << 4);
            ldsm4(Ah, smb + WOFF_HH + ua);
            ldsm4(Al, smb + WOFF_HL + ua);
            #pragma unroll
            for (int ntp = 0; ntp < 2; ntp++) {
                const int rowB = rbB + ntp * 16;
                const uint32_t ab = (uint32_t)(rowB * 128 + (((2 * t + ql) ^ (rowB & 7)) << 4));
                uint32_t Bh[4], Bl[4];
                ldsm4(Bh, smb + WOFF_WH + ab);
                ldsm4(Bl, smb + WOFF_WL + ab);
                mma_bf16(acc[2 * ntp],     Ah, Bh[0], Bh[1]);
                mma_bf16(acc[2 * ntp],     Ah, Bl[0], Bl[1]);
                mma_bf16(acc[2 * ntp],     Al, Bh[0], Bh[1]);
                mma_bf16(acc[2 * ntp + 1], Ah, Bh[2], Bh[3]);
                mma_bf16(acc[2 * ntp + 1], Ah, Bl[2], Bl[3]);
                mma_bf16(acc[2 * ntp + 1], Al, Bh[2], Bh[3]);
            }
        }
    }
    __syncthreads();

    const int r0 = mq * 16 + (lid >> 2), r1 = r0 + 8;
    float s1r0 = 0.f, s2r0 = 0.f, s1r1 = 0.f, s2r1 = 0.f;
    __half* tr = reinterpret_cast<__half*>(sw + WOFF_TR);
    float* ps1 = reinterpret_cast<float*>(sw + WOFF_PS);
    float* ps2 = ps1 + 128;
    #pragma unroll
    for (int nt = 0; nt < 4; nt++) {
        const int d0 = nh * 32 + nt * 8 + (lid & 3) * 2;
        const float a10 = a[d0], a11 = a[d0 + 1];
        const float a20 = a[64 + d0], a21 = a[64 + d0 + 1];
        s1r0 = fmaf(acc[nt][0], a10, fmaf(acc[nt][1], a11, s1r0));
        s2r0 = fmaf(acc[nt][0], a20, fmaf(acc[nt][1], a21, s2r0));
        s1r1 = fmaf(acc[nt][2], a10, fmaf(acc[nt][3], a11, s1r1));
        s2r1 = fmaf(acc[nt][2], a20, fmaf(acc[nt][3], a21, s2r1));
        tr[(d0 + 0) * 64 + r0] = __float2half_rn(acc[nt][0]);
        tr[(d0 + 1) * 64 + r0] = __float2half_rn(acc[nt][1]);
        tr[(d0 + 0) * 64 + r1] = __float2half_rn(acc[nt][2]);
        tr[(d0 + 1) * 64 + r1] = __float2half_rn(acc[nt][3]);
    }
    #pragma unroll
    for (int off = 1; off <= 2; off <<= 1) {
        s1r0 += __shfl_xor_sync(0xffffffffu, s1r0, off);
        s2r0 += __shfl_xor_sync(0xffffffffu, s2r0, off);
        s1r1 += __shfl_xor_sync(0xffffffffu, s1r1, off);
        s2r1 += __shfl_xor_sync(0xffffffffu, s2r1, off);
    }
    if ((lid & 3) == 0) {
        ps1[nh * 64 + r0] = s1r0; ps2[nh * 64 + r0] = s2r0;
        ps1[nh * 64 + r1] = s1r1; ps2[nh * 64 + r1] = s2r1;
    }
    __syncthreads();

    if (tid < 64) {
        const float s1 = ps1[tid] + ps1[64 + tid];
        const float s2 = ps2[tid] + ps2[64 + tid];
        g_s1[gi0 + tid] = s1;
        g_s2[gi0 + tid] = s2;
        g_u[gi0 + tid] = __expf(s2);
        g_v[gi0 + tid] = __expf(ALPHA * s2);
        float m = s2;
        #pragma unroll
        for (int off = 16; off; off >>= 1) m = fmaxf(m, __shfl_down_sync(0xffffffffu, m, off));
        if ((tid & 31) == 0) atomicMax(&g_s2max_u[b], fkey(m));
    }

    #pragma unroll
    for (int c = 0; c < 2; c++) {
        const int idx = tid + 256 * c;
        const int d = idx >> 3;
        const int c8 = idx & 7;
        const uint4 val = *reinterpret_cast<const uint4*>(tr + d * 64 + c8 * 8);
        *reinterpret_cast<uint4*>(g_WhT + ((size_t)(b * DOUT + d)) * NN + rowb + c8 * 8) = val;
    }
}

// ============================================================
// Kernel B: fp16 HMMA GAT main (exact R10 fastest config).
// 256 CTAs x 64 rows, 16 warps (512 thr). Warp = 16 rows x 16 dims.
// 2-stage ping-pong, register prefetch, fp32 build.
// ============================================================
#define GOFF_PHI(s) ((s) * 8192)
#define GOFF_WHI(s) (16384 + (s) * 8192)
#define GOFF_U   32768
#define GOFF_V   40960
#define GOFF_AS  49152
#define GOFF_BS  49408
#define GOFF_ZF  49664
#define GAT_SMEM 49920

__global__ __launch_bounds__(512, 2) void gat_main(const int* __restrict__ adj,
                                                   float* __restrict__ out) {
    extern __shared__ char sm[];
    const uint32_t smb = smem_u32(sm);
    const int tid = threadIdx.x;
    const int wid = tid >> 5, lid = tid & 31;
    const int gi0 = blockIdx.x * 64;
    const int b = gi0 >> 11;

    float* u_sh = reinterpret_cast<float*>(sm + GOFF_U);
    float* v_sh = reinterpret_cast<float*>(sm + GOFF_V);
    float* As = reinterpret_cast<float*>(sm + GOFF_AS);
    float* Bs = reinterpret_cast<float*>(sm + GOFF_BS);
    float* zf = reinterpret_cast<float*>(sm + GOFF_ZF);

    // ---- prologue: copy u/v (512 float4 each); A/B (64 exps) ----
    {
        const float4* us = reinterpret_cast<const float4*>(g_u + b * NN);
        const float4* vs = reinterpret_cast<const float4*>(g_v + b * NN);
        reinterpret_cast<float4*>(u_sh)[tid] = us[tid];
        reinterpret_cast<float4*>(v_sh)[tid] = vs[tid];
    }
    if (tid < 64) {
        const float s2m = funkey(g_s2max_u[b]);
        const float s1 = g_s1[gi0 + tid];
        const float t = s1 + s2m;
        const float m = (t > 0.f) ? t : ALPHA * t;
        As[tid] = 0.5f * __expf(s1 - m);
        Bs[tid] = 0.5f * __expf(ALPHA * s1 - m);
    }
    __syncthreads();

    // ---- build geometry: thread -> rows r2, r2+32; 4 j per row ----
    const int r2 = tid >> 4;            // 0..31
    const int chunk = tid & 15;
    const int chunk4 = chunk * 4;

    float Ar[2], Br[2];
    Ar[0] = As[r2];      Br[0] = Bs[r2];
    Ar[1] = As[r2 + 32]; Br[1] = Bs[r2 + 32];

    float acc[2][4];
    #pragma unroll
    for (int n = 0; n < 2; n++)
        #pragma unroll
        for (int k = 0; k < 4; k++) acc[n][k] = 0.f;
    float zacc[2] = {0.f, 0.f};

    // ---- MMA geometry: warp = rows mq*16.., dims nq*16.. ----
    const int mq = wid & 3, nq = wid >> 2;
    const int rr = lid & 7, q = lid >> 3, qh = q >> 1, ql = q & 1;
    const int rowA = mq * 16 + rr + (ql << 3);
    const uint32_t baseA = (uint32_t)(rowA * 128);
    const int xA = rowA & 7;
    const int rbB = nq * 16 + (qh << 3) + rr;
    const uint32_t baseB = (uint32_t)(rbB * 128);
    const int xB = rbB & 7;

    // ---- W staging: 512 threads x 1 chunk ----
    const int wdrow = tid >> 3, wun = tid & 7;
    const uint32_t wdst = (uint32_t)(wdrow * 128 + ((wun ^ (wdrow & 7)) << 4));
    const __half* wsrc = g_WhT + ((size_t)(b * DOUT + wdrow)) * NN + wun * 8;
    const int* asrc = adj + (size_t)(gi0 + r2) * NN + chunk4;

    // ---- prefetch ----
    int4 adjr[2];
    uint4 pwh;
    adjr[0] = *reinterpret_cast<const int4*>(asrc);
    adjr[1] = *reinterpret_cast<const int4*>(asrc + (size_t)32 * NN);
    pwh = *reinterpret_cast<const uint4*>(wsrc);

    // build stage 0
    {
        *reinterpret_cast<uint4*>(sm + GOFF_WHI(0) + wdst) = pwh;
        const float4 uu = *reinterpret_cast<const float4*>(u_sh + chunk4);
        const float4 vv = *reinterpret_cast<const float4*>(v_sh + chunk4);
        #pragma unroll
        for (int i = 0; i < 2; i++) {
            const int row = r2 + 32 * i;
            const int4 av = adjr[i];
            float4 p;
            p.x = fmaxf(Ar[i] * uu.x, Br[i] * vv.x) * __int_as_float(av.x << 30);
            p.y = fmaxf(Ar[i] * uu.y, Br[i] * vv.y) * __int_as_float(av.y << 30);
            p.z = fmaxf(Ar[i] * uu.z, Br[i] * vv.z) * __int_as_float(av.z << 30);
            p.w = fmaxf(Ar[i] * uu.w, Br[i] * vv.w) * __int_as_float(av.w << 30);
            zacc[i] += (p.x + p.y) + (p.z + p.w);
            const uint32_t swo = (uint32_t)(row * 128 + (((chunk >> 1) ^ (row & 7)) << 4) +
                                            ((chunk & 1) << 3));
            *reinterpret_cast<uint2*>(sm + GOFF_PHI(0) + swo) =
                make_uint2(pkhf2(p.x, p.y), pkhf2(p.z, p.w));
        }
    }
    __syncthreads();

    for (int jt = 0; jt < 32; jt++) {
        const int cur = jt & 1;
        const bool more = (jt < 31);
        const int jn = (jt + 1) * 64;

        if (more) {
            adjr[0] = *reinterpret_cast<const int4*>(asrc + jn);
            adjr[1] = *reinterpret_cast<const int4*>(asrc + (size_t)32 * NN + jn);
            pwh = *reinterpret_cast<const uint4*>(wsrc + jn);
        }

        // ---- MMA on current stage: 4 t x (1 ldsmA + 1 ldsmB + 2 MMA) ----
        {
            const uint32_t oPhi = GOFF_PHI(cur), oWhi = GOFF_WHI(cur);
            #pragma unroll
            for (int t = 0; t < 4; t++) {
                uint32_t Ah[4], Bh[4];
                ldsm4(Ah, smb + oPhi + baseA + (uint32_t)(((2 * t + qh) ^ xA) << 4));
                ldsm4(Bh, smb + oWhi + baseB + (uint32_t)(((2 * t + ql) ^ xB) << 4));
                mma_f16(acc[0], Ah, Bh[0], Bh[1]);
                mma_f16(acc[1], Ah, Bh[2], Bh[3]);
            }
        }

        // ---- build next stage ----
        if (more) {
            const int nxt = cur ^ 1;
            *reinterpret_cast<uint4*>(sm + GOFF_WHI(nxt) + wdst) = pwh;
            const float4 uu = *reinterpret_cast<const float4*>(u_sh + jn + chunk4);
            const float4 vv = *reinterpret_cast<const float4*>(v_sh + jn + chunk4);
            #pragma unroll
            for (int i = 0; i < 2; i++) {
                const int row = r2 + 32 * i;
                const int4 av = adjr[i];
                float4 p;
                p.x = fmaxf(Ar[i] * uu.x, Br[i] * vv.x) * __int_as_float(av.x << 30);
                p.y = fmaxf(Ar[i] * uu.y, Br[i] * vv.y) * __int_as_float(av.y << 30);
                p.z = fmaxf(Ar[i] * uu.z, Br[i] * vv.z) * __int_as_float(av.z << 30);
                p.w = fmaxf(Ar[i] * uu.w, Br[i] * vv.w) * __int_as_float(av.w << 30);
                zacc[i] += (p.x + p.y) + (p.z + p.w);
                const uint32_t swo = (uint32_t)(row * 128 + (((chunk >> 1) ^ (row & 7)) << 4) +
                                                ((chunk & 1) << 3));
                *reinterpret_cast<uint2*>(sm + GOFF_PHI(nxt) + swo) =
                    make_uint2(pkhf2(p.x, p.y), pkhf2(p.z, p.w));
            }
        }
        __syncthreads();
    }

    // ---- Z reduction (alias P_HI(0)): zp[row][chunk] ----
    float* zp = reinterpret_cast<float*>(sm + GOFF_PHI(0));
    zp[r2 * 16 + chunk] = zacc[0];
    zp[(r2 + 32) * 16 + chunk] = zacc[1];
    __syncthreads();
    if (tid < 64) {
        const float* src = zp + tid * 16;
        float z = 0.f;
        #pragma unroll
        for (int t = 0; t < 16; t++) z += src[t];
        zf[tid] = z;
    }
    __syncthreads();

    // ---- normalize + store: warp rows mq*16.., dims nq*16.. ----
    const int r0 = mq * 16 + (lid >> 2), r1 = r0 + 8;
    const float inv0 = 1.f / zf[r0];
    const float inv1 = 1.f / zf[r1];
    float* o0 = out + (size_t)(gi0 + r0) * DOUT + nq * 16 + (lid & 3) * 2;
    float* o1 = out + (size_t)(gi0 + r1) * DOUT + nq * 16 + (lid & 3) * 2;
    #pragma unroll
    for (int n = 0; n < 2; n++) {
        *reinterpret_cast<float2*>(o0 + n * 8) = make_float2(acc[n][0] * inv0, acc[n][1] * inv0);
        *reinterpret_cast<float2*>(o1 + n * 8) = make_float2(acc[n][2] * inv1, acc[n][3] * inv1);
    }
}

// ============================================================
extern "C" void kernel_launch(void* const* d_in, const int* in_sizes, int n_in,
                              void* d_out, int out_size) {
    const float* h   = (const float*)d_in[0];
    const int*   adj = (const int*)d_in[1];
    const float* W   = (const float*)d_in[2];
    const float* a   = (const float*)d_in[3];
    float* out = (float*)d_out;

    cudaFuncSetAttribute(gat_main, cudaFuncAttributeMaxDynamicSharedMemorySize, GAT_SMEM);
    cudaFuncSetAttribute(wh_kernel, cudaFuncAttributeMaxDynamicSharedMemorySize, WH_SMEM);

    wh_kernel<<<(BATCH * NN) / 64, 256, WH_SMEM>>>(h, W, a);
    gat_main<<<(BATCH * NN) / 64, 512, GAT_SMEM>>>(adj, out);
}

// round 16
// speedup vs baseline: 1.4676x; 1.0456x over previous
#include <cuda_runtime.h>
#include <cuda_bf16.h>
#include <cuda_fp16.h>
#include <cstdint>

#define BATCH 8
#define NN    2048
#define KDIM  256
#define DOUT  64
#define ALPHA 0.2f

// ---------------- scratch ----------------
__device__ __half g_WhT[BATCH * DOUT * NN];   // [b][d][j] fp16, 2MB
__device__ float g_s1[BATCH * NN];
__device__ float g_s2[BATCH * NN];
__device__ float g_u[BATCH * NN];             // exp(s2)
__device__ float g_v[BATCH * NN];             // exp(alpha*s2)
__device__ unsigned int g_s2max_u[BATCH];     // order-preserving float keys

// ---------------- helpers ----------------
__device__ __forceinline__ uint32_t smem_u32(const void* p) {
    uint32_t a;
    asm("{ .reg .u64 t; cvta.to.shared.u64 t, %1; cvt.u32.u64 %0, t; }" : "=r"(a) : "l"(p));
    return a;
}
__device__ __forceinline__ void ldsm4(uint32_t (&r)[4], uint32_t addr) {
    asm volatile("ldmatrix.sync.aligned.m8n8.x4.shared.b16 {%0,%1,%2,%3}, [%4];"
                 : "=r"(r[0]), "=r"(r[1]), "=r"(r[2]), "=r"(r[3]) : "r"(addr));
}
__device__ __forceinline__ void mma_f16(float (&d)[4], const uint32_t (&a)[4],
                                        uint32_t b0, uint32_t b1) {
    asm volatile("mma.sync.aligned.m16n8k16.row.col.f32.f16.f16.f32 "
                 "{%0,%1,%2,%3}, {%4,%5,%6,%7}, {%8,%9}, {%0,%1,%2,%3};"
                 : "+f"(d[0]), "+f"(d[1]), "+f"(d[2]), "+f"(d[3])
                 : "r"(a[0]), "r"(a[1]), "r"(a[2]), "r"(a[3]), "r"(b0), "r"(b1));
}
__device__ __forceinline__ uint32_t pkhf2(float x, float y) {
    __half2 t = __floats2half2_rn(x, y);
    return *reinterpret_cast<uint32_t*>(&t);
}
__device__ __forceinline__ uint32_t fkey(float f) {
    const uint32_t b = __float_as_uint(f);
    return b ^ ((uint32_t)((int)b >> 31) | 0x80000000u);
}
__device__ __forceinline__ float funkey(uint32_t k) {
    const uint32_t b = (k & 0x80000000u) ? (k ^ 0x80000000u) : ~k;
    return __uint_as_float(b);
}

// ============================================================
// Kernel A (HMMA fp16 single-plane): Wh = h @ W.
// 256 CTAs x 64 rows, 8 warps, 2 CTAs/SM, distance-1 reg prefetch.
// Emits s1, s2, u, v, s2max key, WhT fp16.
// ============================================================
#define WOFF_H  0
#define WOFF_W  8192
#define WOFF_TR 0
#define WOFF_PS 16384
#define WH_SMEM 17408

__global__ __launch_bounds__(256, 2) void wh_kernel(const float* __restrict__ h,
                                                    const float* __restrict__ W,
                                                    const float* __restrict__ a) {
    extern __shared__ char sw[];
    const uint32_t smb = smem_u32(sw);
    const int tid = threadIdx.x;
    const int wid = tid >> 5, lid = tid & 31;
    const int gi0 = blockIdx.x * 64;
    const int b = gi0 >> 11;
    const int rowb = gi0 & 2047;

    float acc[4][4];
    #pragma unroll
    for (int n = 0; n < 4; n++)
        #pragma unroll
        for (int k = 0; k < 4; k++) acc[n][k] = 0.f;

    const int mq = wid & 3, nh = wid >> 2;
    const int rr = lid & 7, q = lid >> 3, qh = q >> 1, ql = q & 1;
    const int rowA = mq * 16 + rr + (ql << 3);
    const uint32_t baseA = (uint32_t)(rowA * 128);
    const int xA = rowA & 7;
    const int rbB = nh * 32 + (qh << 3) + rr;

    const int hrow = tid >> 2, hq = tid & 3;
    const float* hsrc = h + (size_t)(gi0 + hrow) * KDIM + hq * 16;
    const int wdd = tid >> 2, wkg = tid & 3;

    // ---- distance-1 prefetch buffers ----
    float4 hc[4];
    float wc[16];
    #pragma unroll
    for (int g = 0; g < 2; g++) {
        hc[2 * g]     = *reinterpret_cast<const float4*>(hsrc + g * 8);
        hc[2 * g + 1] = *reinterpret_cast<const float4*>(hsrc + g * 8 + 4);
    }
    #pragma unroll
    for (int t = 0; t < 16; t++)
        wc[t] = W[(wkg * 16 + t) * DOUT + wdd];

    for (int kt = 0; kt < 4; kt++) {
        __syncthreads();
        // ---- stage h chunk [64 rows][64 k] fp16 ----
        #pragma unroll
        for (int g = 0; g < 2; g++) {
            const float4 f0 = hc[2 * g];
            const float4 f1 = hc[2 * g + 1];
            const uint4 hv = make_uint4(pkhf2(f0.x, f0.y), pkhf2(f0.z, f0.w),
                                        pkhf2(f1.x, f1.y), pkhf2(f1.z, f1.w));
            const int gran = hq * 2 + g;
            const uint32_t addr = (uint32_t)(hrow * 128 + ((gran ^ (hrow & 7)) << 4));
            *reinterpret_cast<uint4*>(sw + WOFF_H + addr) = hv;
        }
        // ---- stage W^T chunk [64 d][64 k] fp16 ----
        {
            uint32_t hp[8];
            #pragma unroll
            for (int t = 0; t < 8; t++) hp[t] = pkhf2(wc[2 * t], wc[2 * t + 1]);
            const uint32_t a0 = (uint32_t)(wdd * 128 + (((wkg * 2) ^ (wdd & 7)) << 4));
            const uint32_t a1 = (uint32_t)(wdd * 128 + (((wkg * 2 + 1) ^ (wdd & 7)) << 4));
            *reinterpret_cast<uint4*>(sw + WOFF_W + a0) = make_uint4(hp[0], hp[1], hp[2], hp[3]);
            *reinterpret_cast<uint4*>(sw + WOFF_W + a1) = make_uint4(hp[4], hp[5], hp[6], hp[7]);
        }
        // ---- prefetch kt+1 (covers bar + MMA phase) ----
        if (kt < 3) {
            #pragma unroll
            for (int g = 0; g < 2; g++) {
                hc[2 * g]     = *reinterpret_cast<const float4*>(hsrc + (kt + 1) * 64 + g * 8);
                hc[2 * g + 1] = *reinterpret_cast<const float4*>(hsrc + (kt + 1) * 64 + g * 8 + 4);
            }
            #pragma unroll
            for (int t = 0; t < 16; t++)
                wc[t] = W[((kt + 1) * 64 + wkg * 16 + t) * DOUT + wdd];
        }
        __syncthreads();
        // ---- fp16 MMA ----
        #pragma unroll
        for (int t = 0; t < 4; t++) {
            uint32_t Ah[4];
            ldsm4(Ah, smb + WOFF_H + baseA + (uint32_t)(((2 * t + qh) ^ xA) << 4));
            #pragma unroll
            for (int ntp = 0; ntp < 2; ntp++) {
                const int rowB = rbB + ntp * 16;
                uint32_t Bh[4];
                ldsm4(Bh, smb + WOFF_W + (uint32_t)(rowB * 128 +
                                                    (((2 * t + ql) ^ (rowB & 7)) << 4)));
                mma_f16(acc[2 * ntp],     Ah, Bh[0], Bh[1]);
                mma_f16(acc[2 * ntp + 1], Ah, Bh[2], Bh[3]);
            }
        }
    }
    __syncthreads();

    // ---- epilogue: s1/s2 + fp16 WhT staging ----
    const int r0 = mq * 16 + (lid >> 2), r1 = r0 + 8;
    float s1r0 = 0.f, s2r0 = 0.f, s1r1 = 0.f, s2r1 = 0.f;
    __half* tr = reinterpret_cast<__half*>(sw + WOFF_TR);
    float* ps1 = reinterpret_cast<float*>(sw + WOFF_PS);
    float* ps2 = ps1 + 128;
    #pragma unroll
    for (int nt = 0; nt < 4; nt++) {
        const int d0 = nh * 32 + nt * 8 + (lid & 3) * 2;
        const float a10 = a[d0], a11 = a[d0 + 1];
        const float a20 = a[64 + d0], a21 = a[64 + d0 + 1];
        s1r0 = fmaf(acc[nt][0], a10, fmaf(acc[nt][1], a11, s1r0));
        s2r0 = fmaf(acc[nt][0], a20, fmaf(acc[nt][1], a21, s2r0));
        s1r1 = fmaf(acc[nt][2], a10, fmaf(acc[nt][3], a11, s1r1));
        s2r1 = fmaf(acc[nt][2], a20, fmaf(acc[nt][3], a21, s2r1));
        tr[(d0 + 0) * 64 + r0] = __float2half_rn(acc[nt][0]);
        tr[(d0 + 1) * 64 + r0] = __float2half_rn(acc[nt][1]);
        tr[(d0 + 0) * 64 + r1] = __float2half_rn(acc[nt][2]);
        tr[(d0 + 1) * 64 + r1] = __float2half_rn(acc[nt][3]);
    }
    #pragma unroll
    for (int off = 1; off <= 2; off <<= 1) {
        s1r0 += __shfl_xor_sync(0xffffffffu, s1r0, off);
        s2r0 += __shfl_xor_sync(0xffffffffu, s2r0, off);
        s1r1 += __shfl_xor_sync(0xffffffffu, s1r1, off);
        s2r1 += __shfl_xor_sync(0xffffffffu, s2r1, off);
    }
    if ((lid & 3) == 0) {
        ps1[nh * 64 + r0] = s1r0; ps2[nh * 64 + r0] = s2r0;
        ps1[nh * 64 + r1] = s1r1; ps2[nh * 64 + r1] = s2r1;
    }
    __syncthreads();

    if (tid < 64) {
        const float s1 = ps1[tid] + ps1[64 + tid];
        const float s2 = ps2[tid] + ps2[64 + tid];
        g_s1[gi0 + tid] = s1;
        g_s2[gi0 + tid] = s2;
        g_u[gi0 + tid] = __expf(s2);
        g_v[gi0 + tid] = __expf(ALPHA * s2);
        float m = s2;
        #pragma unroll
        for (int off = 16; off; off >>= 1) m = fmaxf(m, __shfl_down_sync(0xffffffffu, m, off));
        if ((tid & 31) == 0) atomicMax(&g_s2max_u[b], fkey(m));
    }

    #pragma unroll
    for (int c = 0; c < 2; c++) {
        const int idx = tid + 256 * c;
        const int d = idx >> 3;
        const int c8 = idx & 7;
        const uint4 val = *reinterpret_cast<const uint4*>(tr + d * 64 + c8 * 8);
        *reinterpret_cast<uint4*>(g_WhT + ((size_t)(b * DOUT + d)) * NN + rowb + c8 * 8) = val;
    }
}

// ============================================================
// Kernel B: fp16 HMMA GAT main (R10/R15 measured-best config, verbatim).
// 256 CTAs x 64 rows, 16 warps (512 thr). Warp = 16 rows x 16 dims.
// 2-stage ping-pong, register prefetch, fp32 build.
// ============================================================
#define GOFF_PHI(s) ((s) * 8192)
#define GOFF_WHI(s) (16384 + (s) * 8192)
#define GOFF_U   32768
#define GOFF_V   40960
#define GOFF_AS  49152
#define GOFF_BS  49408
#define GOFF_ZF  49664
#define GAT_SMEM 49920

__global__ __launch_bounds__(512, 2) void gat_main(const int* __restrict__ adj,
                                                   float* __restrict__ out) {
    extern __shared__ char sm[];
    const uint32_t smb = smem_u32(sm);
    const int tid = threadIdx.x;
    const int wid = tid >> 5, lid = tid & 31;
    const int gi0 = blockIdx.x * 64;
    const int b = gi0 >> 11;

    float* u_sh = reinterpret_cast<float*>(sm + GOFF_U);
    float* v_sh = reinterpret_cast<float*>(sm + GOFF_V);
    float* As = reinterpret_cast<float*>(sm + GOFF_AS);
    float* Bs = reinterpret_cast<float*>(sm + GOFF_BS);
    float* zf = reinterpret_cast<float*>(sm + GOFF_ZF);

    // ---- prologue: copy u/v (512 float4 each); A/B (64 exps) ----
    {
        const float4* us = reinterpret_cast<const float4*>(g_u + b * NN);
        const float4* vs = reinterpret_cast<const float4*>(g_v + b * NN);
        reinterpret_cast<float4*>(u_sh)[tid] = us[tid];
        reinterpret_cast<float4*>(v_sh)[tid] = vs[tid];
    }
    if (tid < 64) {
        const float s2m = funkey(g_s2max_u[b]);
        const float s1 = g_s1[gi0 + tid];
        const float t = s1 + s2m;
        const float m = (t > 0.f) ? t : ALPHA * t;
        As[tid] = 0.5f * __expf(s1 - m);
        Bs[tid] = 0.5f * __expf(ALPHA * s1 - m);
    }
    __syncthreads();

    // ---- build geometry: thread -> rows r2, r2+32; 4 j per row ----
    const int r2 = tid >> 4;            // 0..31
    const int chunk = tid & 15;
    const int chunk4 = chunk * 4;

    float Ar[2], Br[2];
    Ar[0] = As[r2];      Br[0] = Bs[r2];
    Ar[1] = As[r2 + 32]; Br[1] = Bs[r2 + 32];

    float acc[2][4];
    #pragma unroll
    for (int n = 0; n < 2; n++)
        #pragma unroll
        for (int k = 0; k < 4; k++) acc[n][k] = 0.f;
    float zacc[2] = {0.f, 0.f};

    // ---- MMA geometry: warp = rows mq*16.., dims nq*16.. ----
    const int mq = wid & 3, nq = wid >> 2;
    const int rr = lid & 7, q = lid >> 3, qh = q >> 1, ql = q & 1;
    const int rowA = mq * 16 + rr + (ql << 3);
    const uint32_t baseA = (uint32_t)(rowA * 128);
    const int xA = rowA & 7;
    const int rbB = nq * 16 + (qh << 3) + rr;
    const uint32_t baseB = (uint32_t)(rbB * 128);
    const int xB = rbB & 7;

    // ---- W staging: 512 threads x 1 chunk ----
    const int wdrow = tid >> 3, wun = tid & 7;
    const uint32_t wdst = (uint32_t)(wdrow * 128 + ((wun ^ (wdrow & 7)) << 4));
    const __half* wsrc = g_WhT + ((size_t)(b * DOUT + wdrow)) * NN + wun * 8;
    const int* asrc = adj + (size_t)(gi0 + r2) * NN + chunk4;

    // ---- prefetch ----
    int4 adjr[2];
    uint4 pwh;
    adjr[0] = *reinterpret_cast<const int4*>(asrc);
    adjr[1] = *reinterpret_cast<const int4*>(asrc + (size_t)32 * NN);
    pwh = *reinterpret_cast<const uint4*>(wsrc);

    // build stage 0
    {
        *reinterpret_cast<uint4*>(sm + GOFF_WHI(0) + wdst) = pwh;
        const float4 uu = *reinterpret_cast<const float4*>(u_sh + chunk4);
        const float4 vv = *reinterpret_cast<const float4*>(v_sh + chunk4);
        #pragma unroll
        for (int i = 0; i < 2; i++) {
            const int row = r2 + 32 * i;
            const int4 av = adjr[i];
            float4 p;
            p.x = fmaxf(Ar[i] * uu.x, Br[i] * vv.x) * __int_as_float(av.x << 30);
            p.y = fmaxf(Ar[i] * uu.y, Br[i] * vv.y) * __int_as_float(av.y << 30);
            p.z = fmaxf(Ar[i] * uu.z, Br[i] * vv.z) * __int_as_float(av.z << 30);
            p.w = fmaxf(Ar[i] * uu.w, Br[i] * vv.w) * __int_as_float(av.w << 30);
            zacc[i] += (p.x + p.y) + (p.z + p.w);
            const uint32_t swo = (uint32_t)(row * 128 + (((chunk >> 1) ^ (row & 7)) << 4) +
                                            ((chunk & 1) << 3));
            *reinterpret_cast<uint2*>(sm + GOFF_PHI(0) + swo) =
                make_uint2(pkhf2(p.x, p.y), pkhf2(p.z, p.w));
        }
    }
    __syncthreads();

    for (int jt = 0; jt < 32; jt++) {
        const int cur = jt & 1;
        const bool more = (jt < 31);
        const int jn = (jt + 1) * 64;

        if (more) {
            adjr[0] = *reinterpret_cast<const int4*>(asrc + jn);
            adjr[1] = *reinterpret_cast<const int4*>(asrc + (size_t)32 * NN + jn);
            pwh = *reinterpret_cast<const uint4*>(wsrc + jn);
        }

        // ---- MMA on current stage: 4 t x (1 ldsmA + 1 ldsmB + 2 MMA) ----
        {
            const uint32_t oPhi = GOFF_PHI(cur), oWhi = GOFF_WHI(cur);
            #pragma unroll
            for (int t = 0; t < 4; t++) {
                uint32_t Ah[4], Bh[4];
                ldsm4(Ah, smb + oPhi + baseA + (uint32_t)(((2 * t + qh) ^ xA) << 4));
                ldsm4(Bh, smb + oWhi + baseB + (uint32_t)(((2 * t + ql) ^ xB) << 4));
                mma_f16(acc[0], Ah, Bh[0], Bh[1]);
                mma_f16(acc[1], Ah, Bh[2], Bh[3]);
            }
        }

        // ---- build next stage ----
        if (more) {
            const int nxt = cur ^ 1;
            *reinterpret_cast<uint4*>(sm + GOFF_WHI(nxt) + wdst) = pwh;
            const float4 uu = *reinterpret_cast<const float4*>(u_sh + jn + chunk4);
            const float4 vv = *reinterpret_cast<const float4*>(v_sh + jn + chunk4);
            #pragma unroll
            for (int i = 0; i < 2; i++) {
                const int row = r2 + 32 * i;
                const int4 av = adjr[i];
                float4 p;
                p.x = fmaxf(Ar[i] * uu.x, Br[i] * vv.x) * __int_as_float(av.x << 30);
                p.y = fmaxf(Ar[i] * uu.y, Br[i] * vv.y) * __int_as_float(av.y << 30);
                p.z = fmaxf(Ar[i] * uu.z, Br[i] * vv.z) * __int_as_float(av.z << 30);
                p.w = fmaxf(Ar[i] * uu.w, Br[i] * vv.w) * __int_as_float(av.w << 30);
                zacc[i] += (p.x + p.y) + (p.z + p.w);
                const uint32_t swo = (uint32_t)(row * 128 + (((chunk >> 1) ^ (row & 7)) << 4) +
                                                ((chunk & 1) << 3));
                *reinterpret_cast<uint2*>(sm + GOFF_PHI(nxt) + swo) =
                    make_uint2(pkhf2(p.x, p.y), pkhf2(p.z, p.w));
            }
        }
        __syncthreads();
    }

    // ---- Z reduction (alias P_HI(0)): zp[row][chunk] ----
    float* zp = reinterpret_cast<float*>(sm + GOFF_PHI(0));
    zp[r2 * 16 + chunk] = zacc[0];
    zp[(r2 + 32) * 16 + chunk] = zacc[1];
    __syncthreads();
    if (tid < 64) {
        const float* src = zp + tid * 16;
        float z = 0.f;
        #pragma unroll
        for (int t = 0; t < 16; t++) z += src[t];
        zf[tid] = z;
    }
    __syncthreads();

    // ---- normalize + store: warp rows mq*16.., dims nq*16.. ----
    const int r0 = mq * 16 + (lid >> 2), r1 = r0 + 8;
    const float inv0 = 1.f / zf[r0];
    const float inv1 = 1.f / zf[r1];
    float* o0 = out + (size_t)(gi0 + r0) * DOUT + nq * 16 + (lid & 3) * 2;
    float* o1 = out + (size_t)(gi0 + r1) * DOUT + nq * 16 + (lid & 3) * 2;
    #pragma unroll
    for (int n = 0; n < 2; n++) {
        *reinterpret_cast<float2*>(o0 + n * 8) = make_float2(acc[n][0] * inv0, acc[n][1] * inv0);
        *reinterpret_cast<float2*>(o1 + n * 8) = make_float2(acc[n][2] * inv1, acc[n][3] * inv1);
    }
}

// ============================================================
extern "C" void kernel_launch(void* const* d_in, const int* in_sizes, int n_in,
                              void* d_out, int out_size) {
    const float* h   = (const float*)d_in[0];
    const int*   adj = (const int*)d_in[1];
    const float* W   = (const float*)d_in[2];
    const float* a   = (const float*)d_in[3];
    float* out = (float*)d_out;

    cudaFuncSetAttribute(gat_main, cudaFuncAttributeMaxDynamicSharedMemorySize, GAT_SMEM);
    cudaFuncSetAttribute(wh_kernel, cudaFuncAttributeMaxDynamicSharedMemorySize, WH_SMEM);

    wh_kernel<<<(BATCH * NN) / 64, 256, WH_SMEM>>>(h, W, a);
    gat_main<<<(BATCH * NN) / 64, 512, GAT_SMEM>>>(adj, out);
}